// round 11
// baseline (speedup 1.0000x reference)
#include <cuda_runtime.h>
#include <cuda_bf16.h>

#define BB 2048
#define TT 512
#define KK 32
#define NEG_INF (-3.4e38f)
#define NCTA (148 * 6)

__device__ unsigned g_ctr;
__device__ unsigned g_order[BB];

// Counting sort of items by length, descending. 512 threads, one block.
__global__ void crf_sort(const int* __restrict__ lens)
{
    __shared__ unsigned cnt[512], scan[512], cur[512];
    const int tid = threadIdx.x;
    cnt[tid] = 0;
    __syncthreads();
    for (int i = tid; i < BB; i += 512)
        atomicAdd(&cnt[512 - lens[i]], 1u);     // len 1..512 -> bin 511..0 (desc)
    __syncthreads();
    scan[tid] = cnt[tid];
    __syncthreads();
    for (int off = 1; off < 512; off <<= 1) {
        unsigned v = scan[tid];
        unsigned a = (tid >= off) ? scan[tid - off] : 0u;
        __syncthreads();
        scan[tid] = v + a;
        __syncthreads();
    }
    cur[tid] = scan[tid] - cnt[tid];            // exclusive start of bin
    __syncthreads();
    for (int i = tid; i < BB; i += 512) {
        int bin = 512 - lens[i];
        g_order[atomicAdd(&cur[bin], 1u)] = (unsigned)i;
    }
    if (tid == 0) g_ctr = 0u;
}

// One warp per CTA. Warp pulls a PAIR of adjacent-ranked (similar-length)
// items from the sorted queue and runs both items' recurrences interleaved
// (2 independent dependency chains per warp). Per-chain updates predicated
// by t < len (matches reference masking). Step math identical to R8.
__global__ __launch_bounds__(32) void crf_kernel(
    const float* __restrict__ pot,     // [B,T,K]
    const float* __restrict__ trans,   // [K,K]
    const int*   __restrict__ lens,    // [B]
    const int*   __restrict__ tagidx,  // [B,T]
    float*       __restrict__ out)     // [B*T] tags, [B] best, [B] loglik
{
    const int lane = threadIdx.x;

    __shared__ unsigned char bpA[TT * KK];
    __shared__ unsigned char bpB[TT * KK];
    __shared__ __align__(16) float2 xbufA[2][KK];
    __shared__ __align__(16) float2 xbufB[2][KK];
    __shared__ __align__(16) unsigned char tagsA[TT];
    __shared__ __align__(16) unsigned char tagsB[TT];

    float tc[KK], ec[KK];
#pragma unroll
    for (int j = 0; j < KK; j++) {
        float v = trans[j * KK + lane];
        tc[j] = v;
        ec[j] = __expf(v);
    }

    for (;;) {
        unsigned base = 0;
        if (lane == 0) base = atomicAdd(&g_ctr, 2u);
        base = __shfl_sync(0xffffffffu, base, 0);
        if (base >= BB) break;
        const int bA = (int)g_order[base];
        const int bB = (int)g_order[base + 1];

        const int lenA = lens[bA];
        const int lenB = lens[bB];
        const int lenM = max(lenA, lenB);
        const float* pA = pot + (size_t)bA * (TT * KK);
        const float* pB = pot + (size_t)bB * (TT * KK);

        float aVA = pA[lane], aFA = aVA;
        float aVB = pB[lane], aFB = aVB;
        float mA = __shfl_sync(0xffffffffu, aFA, 0);
        float mB = __shfl_sync(0xffffffffu, aFB, 0);

        float qA0 = pA[1 * KK + lane], qA1 = pA[2 * KK + lane];
        float qA2 = pA[3 * KK + lane], qA3 = pA[4 * KK + lane];
        float qB0 = pB[1 * KK + lane], qB1 = pB[2 * KK + lane];
        float qB2 = pB[3 * KK + lane], qB3 = pB[4 * KK + lane];

        auto step = [&](float ptA, float ptB, int t, int buf) {
            float peA = __expf(aFA - mA);
            float peB = __expf(aFB - mB);
            xbufA[buf][lane] = make_float2(aVA, peA);
            xbufB[buf][lane] = make_float2(aVB, peB);
            __syncwarp();
            const float4* xa4 = (const float4*)xbufA[buf];
            const float4* xb4 = (const float4*)xbufB[buf];

            float am0 = NEG_INF, am1 = NEG_INF, am2 = NEG_INF, am3 = NEG_INF;
            float bm0 = NEG_INF, bm1 = NEG_INF, bm2 = NEG_INF, bm3 = NEG_INF;
            int   ai0 = 0, ai1 = 0, ai2 = 0, ai3 = 0;
            int   bi0 = 0, bi1 = 0, bi2 = 0, bi3 = 0;
            float as0 = 0.f, as1 = 0.f, as2 = 0.f, as3 = 0.f;
            float bs0 = 0.f, bs1 = 0.f, bs2 = 0.f, bs3 = 0.f;
#pragma unroll
            for (int q = 0; q < 8; q++) {
                float4 xa = xa4[2 * q], xb = xa4[2 * q + 1];
                float v0 = xa.x + tc[4*q+0];
                float v1 = xa.z + tc[4*q+1];
                float v2 = xb.x + tc[4*q+2];
                float v3 = xb.z + tc[4*q+3];
                bool g0 = v0 > am0; ai0 = g0 ? (4*q+0) : ai0; am0 = g0 ? v0 : am0;
                bool g1 = v1 > am1; ai1 = g1 ? (4*q+1) : ai1; am1 = g1 ? v1 : am1;
                bool g2 = v2 > am2; ai2 = g2 ? (4*q+2) : ai2; am2 = g2 ? v2 : am2;
                bool g3 = v3 > am3; ai3 = g3 ? (4*q+3) : ai3; am3 = g3 ? v3 : am3;
                as0 += xa.y * ec[4*q+0];
                as1 += xa.w * ec[4*q+1];
                as2 += xb.y * ec[4*q+2];
                as3 += xb.w * ec[4*q+3];

                float4 ya = xb4[2 * q], yb = xb4[2 * q + 1];
                float w0 = ya.x + tc[4*q+0];
                float w1 = ya.z + tc[4*q+1];
                float w2 = yb.x + tc[4*q+2];
                float w3 = yb.z + tc[4*q+3];
                bool h0 = w0 > bm0; bi0 = h0 ? (4*q+0) : bi0; bm0 = h0 ? w0 : bm0;
                bool h1 = w1 > bm1; bi1 = h1 ? (4*q+1) : bi1; bm1 = h1 ? w1 : bm1;
                bool h2 = w2 > bm2; bi2 = h2 ? (4*q+2) : bi2; bm2 = h2 ? w2 : bm2;
                bool h3 = w3 > bm3; bi3 = h3 ? (4*q+3) : bi3; bm3 = h3 ? w3 : bm3;
                bs0 += ya.y * ec[4*q+0];
                bs1 += ya.w * ec[4*q+1];
                bs2 += yb.y * ec[4*q+2];
                bs3 += yb.w * ec[4*q+3];
            }
            float bestA = am0; int argA = ai0;
            bool c1 = (am1 > bestA) || ((am1 == bestA) && (ai1 < argA));
            argA = c1 ? ai1 : argA;  bestA = c1 ? am1 : bestA;
            bool c2 = (am2 > bestA) || ((am2 == bestA) && (ai2 < argA));
            argA = c2 ? ai2 : argA;  bestA = c2 ? am2 : bestA;
            bool c3 = (am3 > bestA) || ((am3 == bestA) && (ai3 < argA));
            argA = c3 ? ai3 : argA;  bestA = c3 ? am3 : bestA;
            float ssA = (as0 + as1) + (as2 + as3);

            float bestB = bm0; int argB = bi0;
            bool d1 = (bm1 > bestB) || ((bm1 == bestB) && (bi1 < argB));
            argB = d1 ? bi1 : argB;  bestB = d1 ? bm1 : bestB;
            bool d2 = (bm2 > bestB) || ((bm2 == bestB) && (bi2 < argB));
            argB = d2 ? bi2 : argB;  bestB = d2 ? bm2 : bestB;
            bool d3 = (bm3 > bestB) || ((bm3 == bestB) && (bi3 < argB));
            argB = d3 ? bi3 : argB;  bestB = d3 ? bm3 : bestB;
            float ssB = (bs0 + bs1) + (bs2 + bs3);

            bpA[t * KK + lane] = (unsigned char)argA;
            bpB[t * KK + lane] = (unsigned char)argB;

            bool uA = t < lenA;
            aVA = uA ? (ptA + bestA) : aVA;
            aFA = uA ? (ptA + (mA + __logf(ssA))) : aFA;
            mA  = __shfl_sync(0xffffffffu, aFA, 0);

            bool uB = t < lenB;
            aVB = uB ? (ptB + bestB) : aVB;
            aFB = uB ? (ptB + (mB + __logf(ssB))) : aFB;
            mB  = __shfl_sync(0xffffffffu, aFB, 0);
        };

        int t = 1;
        for (; t + 3 < lenM; t += 4) {
            int c4 = min(t + 4, TT - 1), c5 = min(t + 5, TT - 1);
            int c6 = min(t + 6, TT - 1), c7 = min(t + 7, TT - 1);
            float nA0 = pA[c4 * KK + lane], nA1 = pA[c5 * KK + lane];
            float nA2 = pA[c6 * KK + lane], nA3 = pA[c7 * KK + lane];
            float nB0 = pB[c4 * KK + lane], nB1 = pB[c5 * KK + lane];
            float nB2 = pB[c6 * KK + lane], nB3 = pB[c7 * KK + lane];
            step(qA0, qB0, t + 0, 1);
            step(qA1, qB1, t + 1, 0);
            step(qA2, qB2, t + 2, 1);
            step(qA3, qB3, t + 3, 0);
            qA0 = nA0; qA1 = nA1; qA2 = nA2; qA3 = nA3;
            qB0 = nB0; qB1 = nB1; qB2 = nB2; qB3 = nB3;
        }
        if (t < lenM) { step(qA0, qB0, t, 1); t++; }
        if (t < lenM) { step(qA1, qB1, t, 0); t++; }
        if (t < lenM) { step(qA2, qB2, t, 1); }
        __syncwarp();

        // ---- terminals: best_score + last_tag (first max index), both ----
        float mvA = aVA, mvB = aVB;
#pragma unroll
        for (int s = 16; s; s >>= 1) {
            mvA = fmaxf(mvA, __shfl_xor_sync(0xffffffffu, mvA, s));
            mvB = fmaxf(mvB, __shfl_xor_sync(0xffffffffu, mvB, s));
        }
        int lastA = __ffs(__ballot_sync(0xffffffffu, aVA == mvA)) - 1;
        int lastB = __ffs(__ballot_sync(0xffffffffu, aVB == mvB)) - 1;

        // ---- exact final logsumexp, both ----
        float mfA = aFA, mfB = aFB;
#pragma unroll
        for (int s = 16; s; s >>= 1) {
            mfA = fmaxf(mfA, __shfl_xor_sync(0xffffffffu, mfA, s));
            mfB = fmaxf(mfB, __shfl_xor_sync(0xffffffffu, mfB, s));
        }
        float exA = __expf(aFA - mfA);
        float exB = __expf(aFB - mfB);
#pragma unroll
        for (int s = 16; s; s >>= 1) {
            exA += __shfl_xor_sync(0xffffffffu, exA, s);
            exB += __shfl_xor_sync(0xffffffffu, exB, s);
        }
        float lnA = mfA + __logf(exA);
        float lnB = mfB + __logf(exB);

        // ---- tags: fill with last tag, backtrace A on lane0, B on lane1 ----
        unsigned repA = (unsigned)lastA * 0x01010101u;
        unsigned repB = (unsigned)lastB * 0x01010101u;
#pragma unroll
        for (int w = 0; w < 4; w++) {
            ((unsigned*)tagsA)[w * 32 + lane] = repA;
            ((unsigned*)tagsB)[w * 32 + lane] = repB;
        }
        __syncwarp();

        if (lane < 2) {
            const unsigned char* bp = (lane == 0) ? bpA : bpB;
            unsigned char* tg = (lane == 0) ? tagsA : tagsB;
            int cur = (lane == 0) ? lastA : lastB;
            int ln  = (lane == 0) ? lenA : lenB;
            for (int tt = ln - 1; tt >= 1; tt--) {
                cur = bp[tt * KK + cur];
                tg[tt - 1] = (unsigned char)cur;
            }
        }
        __syncwarp();

        float* oA = out + (size_t)bA * TT;
        float* oB = out + (size_t)bB * TT;
#pragma unroll
        for (int c = 0; c < 4; c++) {
            uchar4 ua = ((const uchar4*)tagsA)[c * 32 + lane];
            ((float4*)oA)[c * 32 + lane] =
                make_float4((float)ua.x, (float)ua.y, (float)ua.z, (float)ua.w);
            uchar4 ub = ((const uchar4*)tagsB)[c * 32 + lane];
            ((float4*)oB)[c * 32 + lane] =
                make_float4((float)ub.x, (float)ub.y, (float)ub.z, (float)ub.w);
        }

        // ---- gold sequence scores ----
        const int* tiA = tagidx + (size_t)bA * TT;
        const int* tiB = tagidx + (size_t)bB * TT;
        float accA = 0.f, accB = 0.f;
#pragma unroll 4
        for (int tt = lane; tt < TT; tt += 32) {
            int ga = tiA[tt];
            float ua = pA[tt * KK + ga];
            int na = tiA[min(tt + 1, TT - 1)];
            float wa = trans[ga * KK + na];
            accA += (tt < lenA)     ? ua : 0.f;
            accA += (tt < lenA - 1) ? wa : 0.f;
            int gb = tiB[tt];
            float ub = pB[tt * KK + gb];
            int nb = tiB[min(tt + 1, TT - 1)];
            float wb = trans[gb * KK + nb];
            accB += (tt < lenB)     ? ub : 0.f;
            accB += (tt < lenB - 1) ? wb : 0.f;
        }
#pragma unroll
        for (int s = 16; s; s >>= 1) {
            accA += __shfl_xor_sync(0xffffffffu, accA, s);
            accB += __shfl_xor_sync(0xffffffffu, accB, s);
        }

        if (lane == 0) {
            out[(size_t)BB * TT + bA]      = mvA;
            out[(size_t)BB * TT + BB + bA] = accA - lnA;
            out[(size_t)BB * TT + bB]      = mvB;
            out[(size_t)BB * TT + BB + bB] = accB - lnB;
        }
    }
}

extern "C" void kernel_launch(void* const* d_in, const int* in_sizes, int n_in,
                              void* d_out, int out_size) {
    const float* pot = nullptr;
    const float* trn = nullptr;
    const int*   len = nullptr;
    const int*   tgi = nullptr;
    for (int i = 0; i < n_in; i++) {
        switch (in_sizes[i]) {
            case 33554432: pot = (const float*)d_in[i]; break;
            case 1024:     trn = (const float*)d_in[i]; break;
            case 2048:     len = (const int*)d_in[i];   break;
            case 1048576:  tgi = (const int*)d_in[i];   break;
            default: break;
        }
    }
    float* out = (float*)d_out;
    crf_sort<<<1, 512>>>(len);
    crf_kernel<<<NCTA, 32>>>(pot, trn, len, tgi, out);
    (void)out_size;
}

// round 15
// speedup vs baseline: 1.3138x; 1.3138x over previous
#include <cuda_runtime.h>
#include <cuda_bf16.h>

// CRF batched Viterbi+forward, LPT-scheduled dynamic queue. (rev-b source)

#define BB 2048
#define TT 512
#define KK 32
#define NEG_INF (-3.4e38f)
#define NCTA (148 * 13)

__device__ unsigned g_qhead;
__device__ unsigned g_sched[BB];

// Counting sort of items by length, descending (LPT schedule). One block.
__global__ void crf_order_kernel(const int* __restrict__ lens)
{
    __shared__ unsigned hist[512];
    __shared__ unsigned pfx[512];
    __shared__ unsigned slot[512];
    const int tid = threadIdx.x;
    hist[tid] = 0;
    __syncthreads();
    for (int i = tid; i < BB; i += 512)
        atomicAdd(&hist[512 - lens[i]], 1u);    // len 1..512 -> bin 511..0 (desc)
    __syncthreads();
    pfx[tid] = hist[tid];
    __syncthreads();
    for (int off = 1; off < 512; off <<= 1) {
        unsigned v = pfx[tid];
        unsigned a = (tid >= off) ? pfx[tid - off] : 0u;
        __syncthreads();
        pfx[tid] = v + a;
        __syncthreads();
    }
    slot[tid] = pfx[tid] - hist[tid];           // exclusive start of bin
    __syncthreads();
    for (int i = tid; i < BB; i += 512) {
        int bin = 512 - lens[i];
        g_sched[atomicAdd(&slot[bin], 1u)] = (unsigned)i;
    }
    if (tid == 0) g_qhead = 0u;
}

// One warp per CTA; queue dispenses items longest-first (LPT), so all warps
// drain within ~one short item of each other. Step math identical to R8.
__global__ __launch_bounds__(32) void crf_main_kernel(
    const float* __restrict__ pot,     // [B,T,K]
    const float* __restrict__ trans,   // [K,K]
    const int*   __restrict__ lens,    // [B]
    const int*   __restrict__ tagidx,  // [B,T]
    float*       __restrict__ out)     // [B*T] tags, [B] best, [B] loglik
{
    const int lane = threadIdx.x;

    __shared__ unsigned char bp_sm[TT * KK];
    __shared__ __align__(16) float2 xbuf[2][KK];   // (aV, pexp) interleaved
    __shared__ __align__(16) unsigned char tags_sm[TT];

    float tc[KK], ec[KK];
#pragma unroll
    for (int j = 0; j < KK; j++) {
        float v = trans[j * KK + lane];
        tc[j] = v;
        ec[j] = __expf(v);
    }

    for (;;) {
        unsigned r = 0;
        if (lane == 0) r = atomicAdd(&g_qhead, 1u);
        r = __shfl_sync(0xffffffffu, r, 0);
        if (r >= BB) break;
        const int b = (int)g_sched[r];

        const int len = lens[b];
        const float* pb = pot + (size_t)b * (TT * KK);

        float aV = pb[lane];
        float aF = aV;
        float mcur = __shfl_sync(0xffffffffu, aF, 0);

        // prefetch ring, depth 4 (rows 1..4 in-bounds, TT=512)
        float q0 = pb[1 * KK + lane];
        float q1 = pb[2 * KK + lane];
        float q2 = pb[3 * KK + lane];
        float q3 = pb[4 * KK + lane];

        auto step = [&](float pt, int t, int buf) {
            float pexp = __expf(aF - mcur);
            xbuf[buf][lane] = make_float2(aV, pexp);
            __syncwarp();
            const float4* x4 = (const float4*)xbuf[buf];   // 2 j's per float4

            float m0 = NEG_INF, m1 = NEG_INF, m2 = NEG_INF, m3 = NEG_INF;
            int   i0 = 0, i1 = 0, i2 = 0, i3 = 0;
            float s0 = 0.f, s1 = 0.f, s2 = 0.f, s3 = 0.f;
#pragma unroll
            for (int q = 0; q < 8; q++) {
                float4 xa = x4[2 * q];       // j = 4q, 4q+1 : (aV,p,aV,p)
                float4 xb = x4[2 * q + 1];   // j = 4q+2, 4q+3
                float v0 = xa.x + tc[4*q+0];
                float v1 = xa.z + tc[4*q+1];
                float v2 = xb.x + tc[4*q+2];
                float v3 = xb.z + tc[4*q+3];
                bool g0 = v0 > m0; i0 = g0 ? (4*q+0) : i0; m0 = g0 ? v0 : m0;
                bool g1 = v1 > m1; i1 = g1 ? (4*q+1) : i1; m1 = g1 ? v1 : m1;
                bool g2 = v2 > m2; i2 = g2 ? (4*q+2) : i2; m2 = g2 ? v2 : m2;
                bool g3 = v3 > m3; i3 = g3 ? (4*q+3) : i3; m3 = g3 ? v3 : m3;
                s0 += xa.y * ec[4*q+0];
                s1 += xa.w * ec[4*q+1];
                s2 += xb.y * ec[4*q+2];
                s3 += xb.w * ec[4*q+3];
            }
            float best = m0; int arg = i0;
            bool c1 = (m1 > best) || ((m1 == best) && (i1 < arg));
            arg  = c1 ? i1 : arg;  best = c1 ? m1 : best;
            bool c2 = (m2 > best) || ((m2 == best) && (i2 < arg));
            arg  = c2 ? i2 : arg;  best = c2 ? m2 : best;
            bool c3 = (m3 > best) || ((m3 == best) && (i3 < arg));
            arg  = c3 ? i3 : arg;  best = c3 ? m3 : best;
            float ssum = (s0 + s1) + (s2 + s3);

            bp_sm[t * KK + lane] = (unsigned char)arg;
            aV = pt + best;
            aF = pt + (mcur + __logf(ssum));
            mcur = __shfl_sync(0xffffffffu, aF, 0);   // uniform offset = new aF lane 0
        };

        int t = 1;
        for (; t + 3 < len; t += 4) {
            int c4 = min(t + 4, TT - 1), c5 = min(t + 5, TT - 1);
            int c6 = min(t + 6, TT - 1), c7 = min(t + 7, TT - 1);
            float n0 = pb[c4 * KK + lane];
            float n1 = pb[c5 * KK + lane];
            float n2 = pb[c6 * KK + lane];
            float n3 = pb[c7 * KK + lane];
            step(q0, t + 0, 1);
            step(q1, t + 1, 0);
            step(q2, t + 2, 1);
            step(q3, t + 3, 0);
            q0 = n0; q1 = n1; q2 = n2; q3 = n3;
        }
        if (t < len) { step(q0, t, 1); t++; }
        if (t < len) { step(q1, t, 0); t++; }
        if (t < len) { step(q2, t, 1); }
        __syncwarp();

        // ---- Viterbi terminal: best_score + last_tag (first max index) ----
        float mv = aV;
#pragma unroll
        for (int s = 16; s; s >>= 1)
            mv = fmaxf(mv, __shfl_xor_sync(0xffffffffu, mv, s));
        unsigned msk = __ballot_sync(0xffffffffu, aV == mv);
        int last_tag = __ffs(msk) - 1;

        // ---- exact final logsumexp ----
        float mf = aF;
#pragma unroll
        for (int s = 16; s; s >>= 1)
            mf = fmaxf(mf, __shfl_xor_sync(0xffffffffu, mf, s));
        float ex = __expf(aF - mf);
#pragma unroll
        for (int s = 16; s; s >>= 1)
            ex += __shfl_xor_sync(0xffffffffu, ex, s);
        float log_norm = mf + __logf(ex);

        // ---- tags: fill with last_tag, then backtrace over smem ----
        unsigned rep = (unsigned)last_tag * 0x01010101u;
#pragma unroll
        for (int w = 0; w < 4; w++)
            ((unsigned*)tags_sm)[w * 32 + lane] = rep;
        __syncwarp();

        if (lane == 0) {
            int tg = last_tag;
            for (int tt = len - 1; tt >= 1; tt--) {
                tg = bp_sm[tt * KK + tg];
                tags_sm[tt - 1] = (unsigned char)tg;
            }
        }
        __syncwarp();

        float* otags = out + (size_t)b * TT;
#pragma unroll
        for (int c = 0; c < 4; c++) {
            uchar4 u = ((const uchar4*)tags_sm)[c * 32 + lane];
            ((float4*)otags)[c * 32 + lane] =
                make_float4((float)u.x, (float)u.y, (float)u.z, (float)u.w);
        }

        // ---- gold sequence score (branch-free) ----
        const int* ti = tagidx + (size_t)b * TT;
        float acc = 0.f;
#pragma unroll 4
        for (int tt = lane; tt < TT; tt += 32) {
            int tg = ti[tt];
            float u  = pb[tt * KK + tg];
            int   tn = ti[min(tt + 1, TT - 1)];
            float w  = trans[tg * KK + tn];
            acc += (tt < len)     ? u : 0.f;
            acc += (tt < len - 1) ? w : 0.f;
        }
#pragma unroll
        for (int s = 16; s; s >>= 1)
            acc += __shfl_xor_sync(0xffffffffu, acc, s);

        if (lane == 0) {
            out[(size_t)BB * TT + b]      = mv;               // best_score
            out[(size_t)BB * TT + BB + b] = acc - log_norm;   // log_likelihood
        }
    }
}

extern "C" void kernel_launch(void* const* d_in, const int* in_sizes, int n_in,
                              void* d_out, int out_size) {
    const float* pot = nullptr;
    const float* trn = nullptr;
    const int*   len = nullptr;
    const int*   tgi = nullptr;
    for (int i = 0; i < n_in; i++) {
        switch (in_sizes[i]) {
            case 33554432: pot = (const float*)d_in[i]; break;
            case 1024:     trn = (const float*)d_in[i]; break;
            case 2048:     len = (const int*)d_in[i];   break;
            case 1048576:  tgi = (const int*)d_in[i];   break;
            default: break;
        }
    }
    float* out = (float*)d_out;
    crf_order_kernel<<<1, 512>>>(len);
    crf_main_kernel<<<NCTA, 32>>>(pot, trn, len, tgi, out);
    (void)out_size;
}